// round 7
// baseline (speedup 1.0000x reference)
#include <cuda_runtime.h>
#include <cuda_bf16.h>
#include <cstdint>

#define L_SEQ 2048
#define BATCH 8
#define EMB   1024
#define KDIM  1024
#define MTOT  (BATCH * L_SEQ)   // 16384

// ---- GEMM tiling: CTA 128x128, 4 warps (2x2), warp tile 64x64, BK=16 ----
#define BM 128
#define BN 128
#define BK 16
#define NCHUNK (KDIM / BK)      // 64
#define GTHREADS 128
#define NSTAGE 3

// smem rows padded to 48B (32B data + 16B pad): 20-word stride is a perfect
// bank permutation mod 32 -> conflict-free ldmatrix without swizzle.
#define RSTRIDE 48
#define A_HI 0
#define A_LO (BM * RSTRIDE)                  // 6144
#define B_HI (2 * BM * RSTRIDE)              // 12288
#define B_LO (B_HI + BN * RSTRIDE)           // 18432
#define STAGE_BYTES (B_LO + BN * RSTRIDE)    // 24576
#define SMEM_BYTES (NSTAGE * STAGE_BYTES)    // 73728

// ---------------- scratch (device globals) ----------------
__device__ __nv_bfloat16 g_xhi[(size_t)MTOT * KDIM];
__device__ __nv_bfloat16 g_xlo[(size_t)MTOT * KDIM];
__device__ __nv_bfloat16 g_wihi[(size_t)EMB * KDIM];
__device__ __nv_bfloat16 g_wilo[(size_t)EMB * KDIM];
__device__ __nv_bfloat16 g_wohi[(size_t)EMB * KDIM];
__device__ __nv_bfloat16 g_wolo[(size_t)EMB * KDIM];
__device__ float         g_v[(size_t)MTOT * EMB];
__device__ __nv_bfloat16 g_atthi[(size_t)MTOT * EMB];
__device__ __nv_bfloat16 g_attlo[(size_t)MTOT * EMB];
__device__ float         g_cst[BATCH * 2 * 128];

__constant__ int c_pos[8] = {0, 1, 2, 3, 4, 0, 1, 2};
__constant__ float c_wtab[8] = {
    1.0f, 0.60653065971263342f, 0.13533528323661270f, 0.011108996538242306f,
    3.3546262790251185e-4f, 3.7266531720786709e-6f, 1.5229979744712628e-8f,
    2.2897348456455531e-11f
};

// ---------------- PTX helpers ----------------
__device__ __forceinline__ uint32_t smem_u32(const void* p) {
    uint32_t a;
    asm("{ .reg .u64 t; cvta.to.shared.u64 t, %1; cvt.u32.u64 %0, t; }" : "=r"(a) : "l"(p));
    return a;
}
__device__ __forceinline__ void cp16(uint32_t dst, const void* src) {
    asm volatile("cp.async.cg.shared.global [%0], [%1], 16;" :: "r"(dst), "l"(src) : "memory");
}
__device__ __forceinline__ void cp_commit() { asm volatile("cp.async.commit_group;" ::: "memory"); }
__device__ __forceinline__ void cp_wait1()  { asm volatile("cp.async.wait_group 1;" ::: "memory"); }

__device__ __forceinline__ void ldx4(uint32_t* r, uint32_t addr) {
    asm volatile("ldmatrix.sync.aligned.m8n8.x4.shared.b16 {%0,%1,%2,%3}, [%4];"
                 : "=r"(r[0]), "=r"(r[1]), "=r"(r[2]), "=r"(r[3]) : "r"(addr));
}
__device__ __forceinline__ void mma16816(float* c, const uint32_t* a, const uint32_t* b) {
    asm volatile("mma.sync.aligned.m16n8k16.row.col.f32.bf16.bf16.f32 "
                 "{%0,%1,%2,%3}, {%4,%5,%6,%7}, {%8,%9}, {%0,%1,%2,%3};"
                 : "+f"(c[0]), "+f"(c[1]), "+f"(c[2]), "+f"(c[3])
                 : "r"(a[0]), "r"(a[1]), "r"(a[2]), "r"(a[3]), "r"(b[0]), "r"(b[1]));
}

// ---------------------------------------------------------------------------
// bf16x3 mma.sync GEMM:  C[M,N](f32) = (Ah+Al)[M,K] · (Bh+Bl)[N,K]^T
// ---------------------------------------------------------------------------
__device__ __forceinline__ void load_chunk(
    uint32_t sb, int stage, int k0, int row0, int col0,
    const __nv_bfloat16* __restrict__ Ah, const __nv_bfloat16* __restrict__ Al,
    const __nv_bfloat16* __restrict__ Bh, const __nv_bfloat16* __restrict__ Bl, int tid)
{
    // 128 threads: each thread owns one row of A and one row of B, 2x16B each
    const uint32_t st  = sb + stage * STAGE_BYTES;
    const uint32_t off = tid * RSTRIDE;
    const size_t ga = (size_t)(row0 + tid) * KDIM + k0;
    const size_t gb = (size_t)(col0 + tid) * KDIM + k0;
    cp16(st + A_HI + off,      Ah + ga);
    cp16(st + A_HI + off + 16, Ah + ga + 8);
    cp16(st + A_LO + off,      Al + ga);
    cp16(st + A_LO + off + 16, Al + ga + 8);
    cp16(st + B_HI + off,      Bh + gb);
    cp16(st + B_HI + off + 16, Bh + gb + 8);
    cp16(st + B_LO + off,      Bl + gb);
    cp16(st + B_LO + off + 16, Bl + gb + 8);
    cp_commit();
}

__global__ __launch_bounds__(GTHREADS, 2)
void gemm_bf16x3(const __nv_bfloat16* __restrict__ Ah, const __nv_bfloat16* __restrict__ Al,
                 const __nv_bfloat16* __restrict__ Bh, const __nv_bfloat16* __restrict__ Bl,
                 float* __restrict__ C)
{
    extern __shared__ char smem[];
    const uint32_t sb = smem_u32(smem);
    const int tid  = threadIdx.x;
    const int lane = tid & 31, wid = tid >> 5;
    const int wm = (wid & 1) * 64, wn = (wid >> 1) * 64;
    const int row0 = blockIdx.y * BM, col0 = blockIdx.x * BN;

    float acc[4][8][4];
#pragma unroll
    for (int i = 0; i < 4; ++i)
#pragma unroll
        for (int j = 0; j < 8; ++j)
#pragma unroll
            for (int k = 0; k < 4; ++k) acc[i][j][k] = 0.f;

    // per-lane ldmatrix source offsets (within a matrix block)
    const uint32_t a_off = (wm + (lane & 15)) * RSTRIDE + ((lane >> 4) << 4);
    const uint32_t b_off = (wn + (lane & 15)) * RSTRIDE + ((lane >> 4) << 4);

    load_chunk(sb, 0, 0,  row0, col0, Ah, Al, Bh, Bl, tid);
    load_chunk(sb, 1, BK, row0, col0, Ah, Al, Bh, Bl, tid);

    int stage = 0, pstage = 2;
    for (int i = 0; i < NCHUNK; ++i) {
        cp_wait1();              // chunk i landed (<=1 younger group pending)
        __syncthreads();         // chunk i visible AND frags of i-1 (stage pstage) consumed

        // ---- prefetch chunk i+2 into stage pstage (last read at iter i-1,
        // ordered by the barrier above). Empty commit keeps group count. ----
        if (i + 2 < NCHUNK)
            load_chunk(sb, pstage, (i + 2) * BK, row0, col0, Ah, Al, Bh, Bl, tid);
        else
            cp_commit();

        const uint32_t st = sb + stage * STAGE_BYTES;

        // ---- fragment loads for chunk i ----
        uint32_t ah[4][4], al[4][4];
#pragma unroll
        for (int t = 0; t < 4; ++t) {
            const uint32_t addr = st + a_off + t * (16 * RSTRIDE);
            ldx4(ah[t], addr + A_HI);
            ldx4(al[t], addr + A_LO);
        }
        uint32_t bh[8][2], bl[8][2];
#pragma unroll
        for (int p = 0; p < 4; ++p) {
            const uint32_t addr = st + b_off + p * (16 * RSTRIDE);
            uint32_t r[4];
            ldx4(r, addr + B_HI);
            bh[2*p][0] = r[0]; bh[2*p][1] = r[2]; bh[2*p+1][0] = r[1]; bh[2*p+1][1] = r[3];
            ldx4(r, addr + B_LO);
            bl[2*p][0] = r[0]; bl[2*p][1] = r[2]; bl[2*p+1][0] = r[1]; bl[2*p+1][1] = r[3];
        }

        // ---- 96 HMMAs, split-major: consecutive MMAs never share an acc ----
#pragma unroll
        for (int mt = 0; mt < 4; ++mt)
#pragma unroll
            for (int nt = 0; nt < 8; ++nt)
                mma16816(acc[mt][nt], ah[mt], bh[nt]);
#pragma unroll
        for (int mt = 0; mt < 4; ++mt)
#pragma unroll
            for (int nt = 0; nt < 8; ++nt)
                mma16816(acc[mt][nt], ah[mt], bl[nt]);
#pragma unroll
        for (int mt = 0; mt < 4; ++mt)
#pragma unroll
            for (int nt = 0; nt < 8; ++nt)
                mma16816(acc[mt][nt], al[mt], bh[nt]);

        stage  = (stage  == NSTAGE - 1) ? 0 : stage + 1;
        pstage = (pstage == NSTAGE - 1) ? 0 : pstage + 1;
    }

    // epilogue: fp32 direct store
#pragma unroll
    for (int mt = 0; mt < 4; ++mt) {
        const int m = row0 + wm + mt * 16 + (lane >> 2);
#pragma unroll
        for (int nt = 0; nt < 8; ++nt) {
            const int n = col0 + wn + nt * 8 + (lane & 3) * 2;
            *(float2*)(C + (size_t)m * EMB + n)       = make_float2(acc[mt][nt][0], acc[mt][nt][1]);
            *(float2*)(C + (size_t)(m + 8) * EMB + n) = make_float2(acc[mt][nt][2], acc[mt][nt][3]);
        }
    }
}

// ---------------------------------------------------------------------------
// fp32 -> bf16 hi/lo split
// ---------------------------------------------------------------------------
__global__ __launch_bounds__(256)
void split_kernel(const float* __restrict__ src, __nv_bfloat16* __restrict__ hi,
                  __nv_bfloat16* __restrict__ lo, int n)
{
    int i = (blockIdx.x * 256 + threadIdx.x) * 4;
    if (i >= n) return;
    float4 v = *(const float4*)(src + i);
    float f[4] = {v.x, v.y, v.z, v.w};
    __nv_bfloat16 h[4], l[4];
#pragma unroll
    for (int j = 0; j < 4; ++j) {
        h[j] = __float2bfloat16(f[j]);
        l[j] = __float2bfloat16(f[j] - __bfloat162float(h[j]));
    }
    *(uint2*)(hi + i) = *(uint2*)h;
    *(uint2*)(lo + i) = *(uint2*)l;
}

// ---------------------------------------------------------------------------
// attention: banded Gaussian conv + constant heads; emits bf16 hi/lo
// ---------------------------------------------------------------------------
__global__ void attn_const_kernel(const float* __restrict__ v, float* __restrict__ cst)
{
    const int b = blockIdx.x, which = blockIdx.y, p = threadIdx.x;
    const int h = which ? 4 : 3;
    float Z = 0.f, acc = 0.f;
#pragma unroll
    for (int j = 0; j < 8; ++j) {
        const int   k = which ? (L_SEQ - 1 - j) : j;
        const float w = c_wtab[j];
        Z += w;
        acc += w * v[((size_t)b * L_SEQ + k) * EMB + h * 128 + p];
    }
    cst[(b * 2 + which) * 128 + p] = acc / Z;
}

#define QT 16
#define CT 256
#define KT 32

__global__ __launch_bounds__(256)
void attn_kernel(const float* __restrict__ v, __nv_bfloat16* __restrict__ ahi,
                 __nv_bfloat16* __restrict__ alo, const float* __restrict__ cst)
{
    const int b = blockIdx.z, q0 = blockIdx.y * QT, c0 = blockIdx.x * CT;
    const int tid = threadIdx.x;
    __shared__ float vt[KT][CT];

    const float* vb = v + (size_t)b * L_SEQ * EMB;
#pragma unroll
    for (int i = 0; i < 8; ++i) {
        const int id = tid + i * 256;
        const int kb = id >> 6, cc = (id & 63) << 2;
        const int k  = q0 - 8 + kb;
        float4 val = make_float4(0.f, 0.f, 0.f, 0.f);
        if (k >= 0 && k < L_SEQ) val = *(const float4*)(vb + (size_t)k * EMB + c0 + cc);
        *(float4*)&vt[kb][cc] = val;
    }
    __syncthreads();

    const int c = c0 + tid, h = c >> 7, pos = c_pos[h];
    const size_t obase = ((size_t)b * L_SEQ + q0) * EMB + c;

    if (pos <= 2) {
        const int off = (pos == 0) ? 0 : (pos == 1 ? -1 : 1);
#pragma unroll
        for (int qq = 0; qq < QT; ++qq) {
            const int cen = q0 + qq + off;
            const int k0 = max(0, cen - 7), k1 = min(L_SEQ - 1, cen + 7);
            float Z = 0.f, acc = 0.f;
            for (int k = k0; k <= k1; ++k) {
                const int   d = k - cen;
                const float w = c_wtab[d < 0 ? -d : d];
                Z += w;
                acc += w * vt[k - q0 + 8][tid];
            }
            const float r = acc / Z;
            __nv_bfloat16 hh = __float2bfloat16(r);
            ahi[obase + (size_t)qq * EMB] = hh;
            alo[obase + (size_t)qq * EMB] = __float2bfloat16(r - __bfloat162float(hh));
        }
    } else {
        const float r = cst[(b * 2 + (pos == 4)) * 128 + (c & 127)];
        __nv_bfloat16 hh = __float2bfloat16(r);
        __nv_bfloat16 ll = __float2bfloat16(r - __bfloat162float(hh));
#pragma unroll
        for (int qq = 0; qq < QT; ++qq) {
            ahi[obase + (size_t)qq * EMB] = hh;
            alo[obase + (size_t)qq * EMB] = ll;
        }
    }
}

// ---------------------------------------------------------------------------
extern "C" void kernel_launch(void* const* d_in, const int* in_sizes, int n_in,
                              void* d_out, int out_size)
{
    const float* x     = (const float*)d_in[0];
    const float* W_in  = (const float*)d_in[1];
    const float* W_out = (const float*)d_in[2];
    float* out = (float*)d_out;

    __nv_bfloat16 *xhi, *xlo, *wihi, *wilo, *wohi, *wolo, *athi, *atlo;
    float *v, *cst;
    cudaGetSymbolAddress((void**)&xhi,  g_xhi);
    cudaGetSymbolAddress((void**)&xlo,  g_xlo);
    cudaGetSymbolAddress((void**)&wihi, g_wihi);
    cudaGetSymbolAddress((void**)&wilo, g_wilo);
    cudaGetSymbolAddress((void**)&wohi, g_wohi);
    cudaGetSymbolAddress((void**)&wolo, g_wolo);
    cudaGetSymbolAddress((void**)&athi, g_atthi);
    cudaGetSymbolAddress((void**)&atlo, g_attlo);
    cudaGetSymbolAddress((void**)&v,    g_v);
    cudaGetSymbolAddress((void**)&cst,  g_cst);

    static bool attr_done = false;
    if (!attr_done) {
        cudaFuncSetAttribute(gemm_bf16x3, cudaFuncAttributeMaxDynamicSharedMemorySize, SMEM_BYTES);
        attr_done = true;
    }

    const int NX = MTOT * KDIM, NW = EMB * KDIM;
    split_kernel<<<NX / (256 * 4), 256>>>(x, xhi, xlo, NX);
    split_kernel<<<NW / (256 * 4), 256>>>(W_in,  wihi, wilo, NW);
    split_kernel<<<NW / (256 * 4), 256>>>(W_out, wohi, wolo, NW);

    const dim3 ggrid(EMB / BN, MTOT / BM);   // (8, 128)
    gemm_bf16x3<<<ggrid, GTHREADS, SMEM_BYTES>>>(xhi, xlo, wihi, wilo, v);

    attn_const_kernel<<<dim3(BATCH, 2), 128>>>(v, cst);
    attn_kernel<<<dim3(EMB / CT, L_SEQ / QT, BATCH), 256>>>(v, athi, atlo, cst);

    gemm_bf16x3<<<ggrid, GTHREADS, SMEM_BYTES>>>(athi, atlo, wohi, wolo, out);
}